// round 6
// baseline (speedup 1.0000x reference)
#include <cuda_runtime.h>
#include <cuda_bf16.h>

// SudokuDigitsDoubles — exact boolean reduction ("naked pairs" row elimination).
//
// Per (puzzle b, row r):
//   m[c]   = 9-bit candidate mask of cell c
//   pv[c]  = m[c] if popcount(m[c]) == 2 else 0
//   active pattern: appears exactly twice among pv[0..8]
//   erase[c] = OR of active patterns p with p != pv[c]
//   out bit (d,c) = m[c] & ~erase[c]
//
// Round 6: ~0.5% of rows have an active pair, so output == input for 99.5%
// of rows. Phase A is a pure linear float4 copy (LDG.128/STG.128) that also
// deposits candidate bits as bytes in smem. Row leaders then compute the
// pair logic and ONLY rows with an active pair get their 81 floats rewritten.

static constexpr int PUZ = 729;              // floats per puzzle
static constexpr int PPB = 8;                // puzzles per block
static constexpr int NCELL = PPB * 81;       // 648
static constexpr int NFLOAT = PPB * PUZ;     // 5832
static constexpr int NV = NFLOAT / 4;        // 1458 float4s
static constexpr int THREADS = 256;
static constexpr int AITER = (NV + THREADS - 1) / THREADS;      // 6
static constexpr int BITER = (NCELL + THREADS - 1) / THREADS;   // 3

__global__ __launch_bounds__(THREADS, 8)
void sudoku_doubles_kernel(const float* __restrict__ in,
                           float* __restrict__ out,
                           int nPuz)
{
    __shared__ unsigned bits4[NV];   // 4 candidate bits per word, one byte each
    __shared__ int masks[NCELL];

    const int basePuz = blockIdx.x * PPB;
    const bool full = (basePuz + PPB <= nPuz);

    if (full) {
        // ---- Phase A: streaming copy + bit extraction (LDG.128 / STG.128) ----
        const float4* gin  = reinterpret_cast<const float4*>(in  + (size_t)basePuz * PUZ);
        float4*       gout = reinterpret_cast<float4*>(out + (size_t)basePuz * PUZ);
        #pragma unroll
        for (int it = 0; it < AITER; ++it) {
            const int j = threadIdx.x + it * THREADS;
            if (j < NV) {
                const float4 v = gin[j];
                gout[j] = v;
                // values are exactly 0.0f / 1.0f -> bit 23 (exponent LSB)
                const unsigned b0 = (__float_as_uint(v.x) >> 23) & 1u;
                const unsigned b1 = (__float_as_uint(v.y) >> 23) & 1u;
                const unsigned b2 = (__float_as_uint(v.z) >> 23) & 1u;
                const unsigned b3 = (__float_as_uint(v.w) >> 23) & 1u;
                bits4[j] = b0 | (b1 << 8) | (b2 << 16) | (b3 << 24);
            }
        }
        __syncthreads();

        // ---- Phase B1: cell-parallel mask build from byte array ----
        const unsigned char* bb = reinterpret_cast<const unsigned char*>(bits4);
        #pragma unroll
        for (int it = 0; it < BITER; ++it) {
            const int t = threadIdx.x + it * THREADS;
            if (t < NCELL) {
                const int pl = t / 81;
                const int rc = t - pl * 81;
                const unsigned char* p = bb + pl * PUZ + rc;
                int m = 0;
                #pragma unroll
                for (int d = 0; d < 9; d++)
                    m |= ((int)p[d * 81]) << d;
                masks[t] = m;
            }
        }
        __syncthreads();

        // ---- Phase B2 + C: row leaders; rewrite only rows with active pairs ----
        const int t = threadIdx.x;
        if (t < PPB * 9) {
            const int rowBase = 9 * t;   // t = pl*9 + r
            int m[9], pv[9];
            #pragma unroll
            for (int k = 0; k < 9; k++) {
                m[k]  = masks[rowBase + k];
                pv[k] = (__popc(m[k]) == 2) ? m[k] : 0;
            }
            int act = 0, tor = 0;
            #pragma unroll
            for (int j = 0; j < 9; j++) {
                int cc = 0;
                #pragma unroll
                for (int k = 0; k < 9; k++)
                    cc += (pv[k] == pv[j]) ? 1 : 0;
                const bool a = (pv[j] != 0) & (cc == 2);
                act |= a ? (1 << j) : 0;
                tor |= a ? pv[j] : 0;
            }
            if (act) {   // rare: ~0.5% of rows
                const int pl = t / 9;
                const int r  = t - 9 * pl;
                float* o = out + (size_t)(basePuz + pl) * PUZ + r * 9;
                #pragma unroll
                for (int c = 0; c < 9; c++) {
                    int erase;
                    if ((act >> c) & 1) {
                        erase = 0;
                        #pragma unroll
                        for (int jj = 0; jj < 9; jj++)
                            if (((act >> jj) & 1) && pv[jj] != pv[c])
                                erase |= pv[jj];
                    } else {
                        erase = tor;
                    }
                    const int keep = m[c] & ~erase;
                    #pragma unroll
                    for (int d = 0; d < 9; d++)
                        o[d * 81 + c] = ((keep >> d) & 1) ? 1.0f : 0.0f;
                }
            }
        }
    } else {
        // ---- generic tail path (unused when nPuz % PPB == 0) ----
        const int puzCount = nPuz - basePuz;
        if (puzCount <= 0) return;
        const int nCellAct = puzCount * 81;

        for (int t = threadIdx.x; t < nCellAct; t += THREADS) {
            const int pl = t / 81;
            const int rc = t - pl * 81;
            const float* p = in + (size_t)(basePuz + pl) * PUZ + rc;
            int mm = 0;
            #pragma unroll
            for (int d = 0; d < 9; d++)
                mm |= (int)((__float_as_uint(p[d * 81]) >> 23) & 1u) << d;
            masks[t] = mm;
        }
        __syncthreads();

        __shared__ int rowinfo[PPB * 9];
        if (threadIdx.x < puzCount * 9) {
            const int rowBase = 9 * threadIdx.x;
            int pv[9];
            #pragma unroll
            for (int k = 0; k < 9; k++) {
                const int mk = masks[rowBase + k];
                pv[k] = (__popc(mk) == 2) ? mk : 0;
            }
            int act = 0, tor = 0;
            #pragma unroll
            for (int j = 0; j < 9; j++) {
                int cc = 0;
                #pragma unroll
                for (int k = 0; k < 9; k++)
                    cc += (pv[k] == pv[j]) ? 1 : 0;
                const bool a = (pv[j] != 0) & (cc == 2);
                act |= a ? (1 << j) : 0;
                tor |= a ? pv[j] : 0;
            }
            rowinfo[threadIdx.x] = tor | (act << 16);
        }
        __syncthreads();

        for (int j = threadIdx.x; j < nCellAct; j += THREADS) {
            const int row = j / 9;
            const int c   = j - 9 * row;
            const int m   = masks[j];
            const int info = rowinfo[row];
            const int act  = info >> 16;
            int erase;
            if ((act >> c) & 1) {
                erase = 0;
                #pragma unroll
                for (int jj = 0; jj < 9; jj++)
                    if ((act >> jj) & 1) {
                        const int pj = masks[9 * row + jj];
                        if (pj != m) erase |= pj;
                    }
            } else {
                erase = info & 0xFFFF;
            }
            const int keep = m & ~erase;
            const int pl = j / 81;
            const int rc = j - pl * 81;
            float* p = out + (size_t)(basePuz + pl) * PUZ + rc;
            #pragma unroll
            for (int d = 0; d < 9; d++)
                p[d * 81] = ((keep >> d) & 1) ? 1.0f : 0.0f;
        }
    }
}

extern "C" void kernel_launch(void* const* d_in, const int* in_sizes, int n_in,
                              void* d_out, int out_size)
{
    const float* mask = (const float*)d_in[0];
    float* out = (float*)d_out;
    const int nPuz = in_sizes[0] / PUZ;   // 32768
    const int grid = (nPuz + PPB - 1) / PPB;
    sudoku_doubles_kernel<<<grid, THREADS>>>(mask, out, nPuz);
}